// round 1
// baseline (speedup 1.0000x reference)
#include <cuda_runtime.h>

#define NN 100000
#define EE 3200000
#define TB 256

// ---------------- scratch (device globals; no allocation allowed) ----------
__device__ __align__(16) float g_deg[NN];        // degree, then deg^-1/2 in place
__device__ __align__(16) float g_norm[EE];       // per-edge gcn norm
__device__ __align__(16) float g_Z[NN * 48];     // conv1 message source [N][K*16]
__device__ __align__(16) float g_Y[NN * 48];     // conv1 scatter target
__device__ __align__(16) float g_root[NN * 48];  // conv1 root/skip term
__device__ __align__(16) float g_Z2[NN * 4];     // conv2 (K=3 padded to 4)
__device__ __align__(16) float g_Y2[NN * 4];
__device__ __align__(16) float g_root2[NN * 4];

__device__ __forceinline__ void red_add_v4(float* addr, float4 v) {
    asm volatile("red.global.add.v4.f32 [%0], {%1,%2,%3,%4};"
                 :: "l"(addr), "f"(v.x), "f"(v.y), "f"(v.z), "f"(v.w)
                 : "memory");
}

// ---------------- gcn_norm -------------------------------------------------
__global__ void k_zero_deg() {
    int n = blockIdx.x * blockDim.x + threadIdx.x;
    if (n < NN) g_deg[n] = 0.f;
}

__global__ void k_deg(const int* __restrict__ col, const float* __restrict__ ew) {
    int e = blockIdx.x * blockDim.x + threadIdx.x;
    if (e >= EE) return;
    atomicAdd(&g_deg[col[e]], ew[e]);
}

__global__ void k_dis() {
    int n = blockIdx.x * blockDim.x + threadIdx.x;
    if (n >= NN) return;
    float d = g_deg[n];
    g_deg[n] = (d > 0.f) ? rsqrtf(fmaxf(d, 1e-12f)) : 0.f;
}

__global__ void k_norm(const int* __restrict__ row, const int* __restrict__ col,
                       const float* __restrict__ ew) {
    int e = blockIdx.x * blockDim.x + threadIdx.x;
    if (e >= EE) return;
    g_norm[e] = g_deg[row[e]] * ew[e] * g_deg[col[e]];
}

// ---------------- conv1 init: Z = x*init_w, root = x*root_w + bias, Y = 0 --
__global__ void k_init1(const float* __restrict__ x, const float* __restrict__ iw,
                        const float* __restrict__ rw, const float* __restrict__ bias) {
    __shared__ float s_iw[48], s_rw[48], s_b[48];
    if (threadIdx.x < 48) {
        s_iw[threadIdx.x] = iw[threadIdx.x];
        s_rw[threadIdx.x] = rw[threadIdx.x];
        s_b[threadIdx.x]  = bias[threadIdx.x];
    }
    __syncthreads();
    int n = blockIdx.x * blockDim.x + threadIdx.x;
    if (n >= NN) return;
    float xv = x[n];
    float* z = g_Z + (size_t)n * 48;
    float* r = g_root + (size_t)n * 48;
    float* y = g_Y + (size_t)n * 48;
#pragma unroll
    for (int i = 0; i < 48; i++) {
        z[i] = xv * s_iw[i];
        r[i] = xv * s_rw[i] + s_b[i];
        y[i] = 0.f;
    }
}

// ---------------- conv1 edge SpMM: Y[col] += norm * Z[row] -----------------
// 12 threads per edge, one float4 chunk each -> coalesced 192B gather/scatter.
__global__ void k_edge48(const int* __restrict__ row, const int* __restrict__ col) {
    long long t = (long long)blockIdx.x * blockDim.x + threadIdx.x;
    if (t >= (long long)EE * 12) return;
    int e = (int)(t / 12);
    int i = (int)(t - (long long)e * 12);
    int r = __ldg(row + e);
    int c = __ldg(col + e);
    float w = g_norm[e];
    float4 z = *(const float4*)(g_Z + (size_t)r * 48 + i * 4);
    z.x *= w; z.y *= w; z.z *= w; z.w *= w;
    red_add_v4(g_Y + (size_t)c * 48 + i * 4, z);
}

// ---------------- conv1 node update (t < 3): out=relu(Y+root); Z=out@W; Y=0
__global__ void k_node1_mid(const float* __restrict__ w) {  // w: [3][16][16]
    __shared__ float sw[768];
    for (int i = threadIdx.x; i < 768; i += blockDim.x) sw[i] = w[i];
    __syncthreads();
    int n = blockIdx.x * blockDim.x + threadIdx.x;
    if (n >= NN) return;
    float4* yp = (float4*)(g_Y + (size_t)n * 48);
    const float4* rp = (const float4*)(g_root + (size_t)n * 48);
    float o[48];
#pragma unroll
    for (int i = 0; i < 12; i++) {
        float4 y = yp[i];
        float4 r = rp[i];
        o[4 * i + 0] = fmaxf(y.x + r.x, 0.f);
        o[4 * i + 1] = fmaxf(y.y + r.y, 0.f);
        o[4 * i + 2] = fmaxf(y.z + r.z, 0.f);
        o[4 * i + 3] = fmaxf(y.w + r.w, 0.f);
        yp[i] = make_float4(0.f, 0.f, 0.f, 0.f);  // re-zero for next iteration
    }
    float* zp = g_Z + (size_t)n * 48;
#pragma unroll
    for (int k = 0; k < 3; k++) {
#pragma unroll
        for (int p = 0; p < 16; p += 4) {
            float4 acc = make_float4(0.f, 0.f, 0.f, 0.f);
#pragma unroll
            for (int q = 0; q < 16; q++) {
                float ov = o[k * 16 + q];
                const float* wq = &sw[k * 256 + q * 16 + p];
                acc.x += ov * wq[0];
                acc.y += ov * wq[1];
                acc.z += ov * wq[2];
                acc.w += ov * wq[3];
            }
            *(float4*)(zp + k * 16 + p) = acc;
        }
    }
}

// ---------------- conv1 final (t == 3) + BN + ReLU + conv2 init ------------
__global__ void k_node1_last(const float* __restrict__ gamma, const float* __restrict__ beta,
                             const float* __restrict__ mean,  const float* __restrict__ var,
                             const float* __restrict__ iw2,   const float* __restrict__ rw2,
                             const float* __restrict__ b2) {
    __shared__ float s_scale[16], s_shift[16], s_iw2[48], s_rw2[48], s_b2[3];
    if (threadIdx.x < 16) {
        float sc = gamma[threadIdx.x] * rsqrtf(var[threadIdx.x] + 1e-5f);
        s_scale[threadIdx.x] = sc;
        s_shift[threadIdx.x] = beta[threadIdx.x] - mean[threadIdx.x] * sc;
    }
    if (threadIdx.x < 48) {
        s_iw2[threadIdx.x] = iw2[threadIdx.x];
        s_rw2[threadIdx.x] = rw2[threadIdx.x];
    }
    if (threadIdx.x < 3) s_b2[threadIdx.x] = b2[threadIdx.x];
    __syncthreads();
    int n = blockIdx.x * blockDim.x + threadIdx.x;
    if (n >= NN) return;
    const float* yp = g_Y + (size_t)n * 48;
    const float* rp = g_root + (size_t)n * 48;
    float h[16];
#pragma unroll
    for (int f = 0; f < 16; f++) {
        float a = fmaxf(yp[f] + rp[f], 0.f)
                + fmaxf(yp[16 + f] + rp[16 + f], 0.f)
                + fmaxf(yp[32 + f] + rp[32 + f], 0.f);
        a *= (1.f / 3.f);                       // mean over K stacks
        a = a * s_scale[f] + s_shift[f];        // BatchNorm (eval)
        h[f] = fmaxf(a, 0.f);                   // ReLU
    }
    float z[3], r2[3];
#pragma unroll
    for (int k = 0; k < 3; k++) {
        float za = 0.f, ra = 0.f;
#pragma unroll
        for (int f = 0; f < 16; f++) {
            za += h[f] * s_iw2[k * 16 + f];
            ra += h[f] * s_rw2[k * 16 + f];
        }
        z[k] = za;
        r2[k] = ra + s_b2[k];
    }
    *(float4*)(g_Z2 + (size_t)n * 4)    = make_float4(z[0], z[1], z[2], 0.f);
    *(float4*)(g_root2 + (size_t)n * 4) = make_float4(r2[0], r2[1], r2[2], 0.f);
    *(float4*)(g_Y2 + (size_t)n * 4)    = make_float4(0.f, 0.f, 0.f, 0.f);
}

// ---------------- conv2 edge SpMM (K padded to 4 floats/node) --------------
__global__ void k_edge4(const int* __restrict__ row, const int* __restrict__ col) {
    int e = blockIdx.x * blockDim.x + threadIdx.x;
    if (e >= EE) return;
    int r = __ldg(row + e);
    int c = __ldg(col + e);
    float w = g_norm[e];
    float4 z = *(const float4*)(g_Z2 + (size_t)r * 4);
    z.x *= w; z.y *= w; z.z *= w; z.w *= w;   // lane 3 is 0, stays 0
    red_add_v4(g_Y2 + (size_t)c * 4, z);
}

// ---------------- conv2 node update (t < 3, act=None) ----------------------
__global__ void k_node2_mid(const float* __restrict__ w2) {  // w2: [3]
    int n = blockIdx.x * blockDim.x + threadIdx.x;
    if (n >= NN) return;
    float w0 = __ldg(w2 + 0), w1 = __ldg(w2 + 1), w2v = __ldg(w2 + 2);
    float4 y = *(float4*)(g_Y2 + (size_t)n * 4);
    float4 r = *(const float4*)(g_root2 + (size_t)n * 4);
    float4 z;
    z.x = (y.x + r.x) * w0;
    z.y = (y.y + r.y) * w1;
    z.z = (y.z + r.z) * w2v;
    z.w = 0.f;
    *(float4*)(g_Z2 + (size_t)n * 4) = z;
    *(float4*)(g_Y2 + (size_t)n * 4) = make_float4(0.f, 0.f, 0.f, 0.f);
}

// ---------------- conv2 final: mean over stacks + sigmoid ------------------
__global__ void k_node2_last(float* __restrict__ out) {
    int n = blockIdx.x * blockDim.x + threadIdx.x;
    if (n >= NN) return;
    float4 y = *(const float4*)(g_Y2 + (size_t)n * 4);
    float4 r = *(const float4*)(g_root2 + (size_t)n * 4);
    float s = ((y.x + r.x) + (y.y + r.y) + (y.z + r.z)) * (1.f / 3.f);
    out[n] = 1.f / (1.f + expf(-s));
}

// ---------------- launch ---------------------------------------------------
extern "C" void kernel_launch(void* const* d_in, const int* in_sizes, int n_in,
                              void* d_out, int out_size) {
    const float* x     = (const float*)d_in[0];
    const int*   ei    = (const int*)d_in[1];
    const float* ew    = (const float*)d_in[2];
    const float* c1_iw = (const float*)d_in[3];
    const float* c1_w  = (const float*)d_in[4];
    const float* c1_rw = (const float*)d_in[5];
    const float* c1_b  = (const float*)d_in[6];
    const float* bn_g  = (const float*)d_in[7];
    const float* bn_b  = (const float*)d_in[8];
    const float* bn_m  = (const float*)d_in[9];
    const float* bn_v  = (const float*)d_in[10];
    const float* c2_iw = (const float*)d_in[11];
    const float* c2_w  = (const float*)d_in[12];
    const float* c2_rw = (const float*)d_in[13];
    const float* c2_b  = (const float*)d_in[14];
    float* out = (float*)d_out;

    const int* row = ei;        // edge_index[0]
    const int* col = ei + EE;   // edge_index[1]

    const int GN = (NN + TB - 1) / TB;
    const int GE = (EE + TB - 1) / TB;
    const long long W48 = (long long)EE * 12;
    const int GE12 = (int)((W48 + TB - 1) / TB);

    // gcn_norm
    k_zero_deg<<<GN, TB>>>();
    k_deg<<<GE, TB>>>(col, ew);
    k_dis<<<GN, TB>>>();
    k_norm<<<GE, TB>>>(row, col, ew);

    // conv1 (T = 4, shared weights)
    k_init1<<<GN, TB>>>(x, c1_iw, c1_rw, c1_b);
    for (int t = 0; t < 4; t++) {
        k_edge48<<<GE12, TB>>>(row, col);
        if (t < 3)
            k_node1_mid<<<GN, TB>>>(c1_w);
        else
            k_node1_last<<<GN, TB>>>(bn_g, bn_b, bn_m, bn_v, c2_iw, c2_rw, c2_b);
    }

    // conv2 (T = 4)
    for (int t = 0; t < 4; t++) {
        k_edge4<<<GE, TB>>>(row, col);
        if (t < 3)
            k_node2_mid<<<GN, TB>>>(c2_w);
        else
            k_node2_last<<<GN, TB>>>(out);
    }
    (void)in_sizes; (void)n_in; (void)out_size;
}

// round 5
// speedup vs baseline: 2.1081x; 2.1081x over previous
#include <cuda_runtime.h>

#define NN 100000
#define EE 3200000

// ---------------- scratch (device globals; ~70 MB total) -------------------
__device__ __align__(16) int   g_cnt[NN];        // histogram, then scatter cursor
__device__ __align__(16) float g_dis[NN];        // weighted degree, then deg^-1/2
__device__ __align__(16) int   g_off[NN + 1];    // CSR offsets (by col)
__device__ __align__(16) int   g_bsum[128];
__device__ __align__(16) int   g_bsum2[128];
__device__ __align__(16) int2  g_csr[EE];        // (row, norm-as-int) grouped by col
__device__ __align__(16) float g_Lx[NN];         // Lx (rank-1 first iteration)
__device__ __align__(16) float g_A[NN * 48];     // conv1 state  out_t
__device__ __align__(16) float g_Y[NN * 48];     // raw aggregate L*out_t
__device__ __align__(16) float g_Z2a[NN * 4];    // conv2 ping (K=3 padded to 4)
__device__ __align__(16) float g_Z2b[NN * 4];    // conv2 pong
__device__ __align__(16) float g_root2[NN * 4];

// ---------------- CSR build ------------------------------------------------
__global__ void __launch_bounds__(256) k_zero() {
    int n = blockIdx.x * blockDim.x + threadIdx.x;
    if (n < NN) { g_cnt[n] = 0; g_dis[n] = 0.f; }
}

__global__ void __launch_bounds__(256) k_hist(const int* __restrict__ col,
                                              const float* __restrict__ ew) {
    int e = blockIdx.x * blockDim.x + threadIdx.x;
    if (e >= EE) return;
    int c = col[e];
    atomicAdd(&g_cnt[c], 1);
    atomicAdd(&g_dis[c], ew[e]);
}

__global__ void __launch_bounds__(256) k_dis() {
    int n = blockIdx.x * blockDim.x + threadIdx.x;
    if (n >= NN) return;
    float d = g_dis[n];
    g_dis[n] = (d > 0.f) ? rsqrtf(fmaxf(d, 1e-12f)) : 0.f;
}

__global__ void __launch_bounds__(1024) k_scan1() {
    __shared__ int s[1024];
    int i = blockIdx.x * 1024 + threadIdx.x;
    int v = (i < NN) ? g_cnt[i] : 0;
    s[threadIdx.x] = v;
    __syncthreads();
#pragma unroll
    for (int off = 1; off < 1024; off <<= 1) {
        int t = (threadIdx.x >= off) ? s[threadIdx.x - off] : 0;
        __syncthreads();
        s[threadIdx.x] += t;
        __syncthreads();
    }
    if (i < NN) g_off[i] = s[threadIdx.x] - v;  // exclusive within block
    if (threadIdx.x == 1023) g_bsum[blockIdx.x] = s[1023];
}

__global__ void __launch_bounds__(32) k_scan2(int nb) {
    if (threadIdx.x == 0 && blockIdx.x == 0) {
        int acc = 0;
        for (int b = 0; b < nb; b++) { g_bsum2[b] = acc; acc += g_bsum[b]; }
    }
}

__global__ void __launch_bounds__(256) k_scan3() {
    int i = blockIdx.x * blockDim.x + threadIdx.x;
    if (i < NN) {
        int v = g_off[i] + g_bsum2[i >> 10];
        g_off[i] = v;
        g_cnt[i] = v;   // reuse histogram array as scatter cursor
    }
    if (i == 0) g_off[NN] = EE;
}

__global__ void __launch_bounds__(256) k_scatter(const int* __restrict__ row,
                                                 const int* __restrict__ col,
                                                 const float* __restrict__ ew) {
    int e = blockIdx.x * blockDim.x + threadIdx.x;
    if (e >= EE) return;
    int r = row[e], c = col[e];
    float nm = g_dis[r] * ew[e] * g_dis[c];
    int p = atomicAdd(&g_cnt[c], 1);
    g_csr[p] = make_int2(r, __float_as_int(nm));
}

// ---------------- conv1 first iteration: scalar SpMV (rank-1 trick) --------
__global__ void __launch_bounds__(256) k_Lx(const float* __restrict__ x) {
    int wid = (blockIdx.x * blockDim.x + threadIdx.x) >> 5;
    int lane = threadIdx.x & 31;
    if (wid >= NN) return;
    int beg = g_off[wid], end = g_off[wid + 1];
    float acc = 0.f;
    for (int p = beg + lane; p < end; p += 32) {
        int2 ent = __ldg(&g_csr[p]);
        acc += __int_as_float(ent.y) * __ldg(x + ent.x);
    }
#pragma unroll
    for (int o = 16; o; o >>= 1) acc += __shfl_xor_sync(0xffffffffu, acc, o);
    if (lane == 0) g_Lx[wid] = acc;
}

// out_1 = relu((Lx)*iw + x*rw + b)  -> g_A
__global__ void __launch_bounds__(256) k_post0(const float* __restrict__ x,
                                               const float* __restrict__ iw,
                                               const float* __restrict__ rw,
                                               const float* __restrict__ bias) {
    __shared__ float siw[48], srw[48], sb[48];
    if (threadIdx.x < 48) {
        siw[threadIdx.x] = iw[threadIdx.x];
        srw[threadIdx.x] = rw[threadIdx.x];
        sb[threadIdx.x]  = bias[threadIdx.x];
    }
    __syncthreads();
    int n = blockIdx.x * blockDim.x + threadIdx.x;
    if (n >= NN) return;
    float s0 = x[n], s1 = g_Lx[n];
    float4* A = (float4*)(g_A + (size_t)n * 48);
#pragma unroll
    for (int i = 0; i < 12; i++) {
        float4 a;
        a.x = fmaxf(s1 * siw[4*i+0] + s0 * srw[4*i+0] + sb[4*i+0], 0.f);
        a.y = fmaxf(s1 * siw[4*i+1] + s0 * srw[4*i+1] + sb[4*i+1], 0.f);
        a.z = fmaxf(s1 * siw[4*i+2] + s0 * srw[4*i+2] + sb[4*i+2], 0.f);
        a.w = fmaxf(s1 * siw[4*i+3] + s0 * srw[4*i+3] + sb[4*i+3], 0.f);
        A[i] = a;
    }
}

// ---------------- conv1 heavy gather: g_Y[n] = sum norm * g_A[row] ---------
// 12-thread groups, 32 nodes per 384-thread block. No smem, tiny regs, no atomics.
__global__ void __launch_bounds__(384) k_gath48() {
    int gid = threadIdx.x / 12;
    int l = threadIdx.x - gid * 12;
    int n = blockIdx.x * 32 + gid;
    if (n >= NN) return;
    int beg = g_off[n], end = g_off[n + 1];
    float4 acc = make_float4(0.f, 0.f, 0.f, 0.f);
    for (int p = beg; p < end; ++p) {
        int2 ent = __ldg(&g_csr[p]);
        float w = __int_as_float(ent.y);
        float4 v = *(const float4*)(g_A + (size_t)ent.x * 48 + l * 4);
        acc.x += w * v.x; acc.y += w * v.y; acc.z += w * v.z; acc.w += w * v.w;
    }
    *(float4*)(g_Y + (size_t)n * 48 + l * 4) = acc;
}

// ---------------- conv1 node update (mid): A = relu(Y@W + x*rw + b) --------
__global__ void __launch_bounds__(256) k_node_mid(const float* __restrict__ x,
                                                  const float* __restrict__ W,
                                                  const float* __restrict__ rw,
                                                  const float* __restrict__ bias) {
    __shared__ float sW[768], srw[48], sb[48];
    for (int i = threadIdx.x; i < 768; i += blockDim.x) sW[i] = W[i];
    if (threadIdx.x < 48) {
        srw[threadIdx.x] = rw[threadIdx.x];
        sb[threadIdx.x]  = bias[threadIdx.x];
    }
    __syncthreads();
    int n = blockIdx.x * blockDim.x + threadIdx.x;
    if (n >= NN) return;
    float xv = x[n];
    const float* Y = g_Y + (size_t)n * 48;
    float* A = g_A + (size_t)n * 48;
#pragma unroll
    for (int k = 0; k < 3; k++) {
        float y[16];
#pragma unroll
        for (int q = 0; q < 16; q++) y[q] = Y[k * 16 + q];
#pragma unroll
        for (int p = 0; p < 16; p += 4) {
            float4 o;
            o.x = xv * srw[k*16 + p + 0] + sb[k*16 + p + 0];
            o.y = xv * srw[k*16 + p + 1] + sb[k*16 + p + 1];
            o.z = xv * srw[k*16 + p + 2] + sb[k*16 + p + 2];
            o.w = xv * srw[k*16 + p + 3] + sb[k*16 + p + 3];
#pragma unroll
            for (int q = 0; q < 16; q++) {
                float yv = y[q];
                const float* wq = &sW[k * 256 + q * 16 + p];
                o.x += yv * wq[0];
                o.y += yv * wq[1];
                o.z += yv * wq[2];
                o.w += yv * wq[3];
            }
            o.x = fmaxf(o.x, 0.f); o.y = fmaxf(o.y, 0.f);
            o.z = fmaxf(o.z, 0.f); o.w = fmaxf(o.w, 0.f);
            *(float4*)(A + k * 16 + p) = o;
        }
    }
}

// ---------------- conv1 final node update + BN + ReLU + conv2 init ---------
__global__ void __launch_bounds__(256) k_node_last(
    const float* __restrict__ x, const float* __restrict__ W,
    const float* __restrict__ rw, const float* __restrict__ bias,
    const float* __restrict__ gamma, const float* __restrict__ beta,
    const float* __restrict__ mean,  const float* __restrict__ var,
    const float* __restrict__ iw2,   const float* __restrict__ rw2,
    const float* __restrict__ b2) {
    __shared__ float sW[768], srw[48], sb[48];
    __shared__ float sscale[16], sshift[16], siw2[48], srw2[48], sb2[3];
    for (int i = threadIdx.x; i < 768; i += blockDim.x) sW[i] = W[i];
    if (threadIdx.x < 48) {
        srw[threadIdx.x] = rw[threadIdx.x];
        sb[threadIdx.x]  = bias[threadIdx.x];
    }
    if (threadIdx.x >= 64 && threadIdx.x < 80) {
        int f = threadIdx.x - 64;
        float sc = gamma[f] * rsqrtf(var[f] + 1e-5f);
        sscale[f] = sc;
        sshift[f] = beta[f] - mean[f] * sc;
    }
    if (threadIdx.x >= 96 && threadIdx.x < 144) {
        siw2[threadIdx.x - 96] = iw2[threadIdx.x - 96];
        srw2[threadIdx.x - 96] = rw2[threadIdx.x - 96];
    }
    if (threadIdx.x >= 160 && threadIdx.x < 163) sb2[threadIdx.x - 160] = b2[threadIdx.x - 160];
    __syncthreads();
    int n = blockIdx.x * blockDim.x + threadIdx.x;
    if (n >= NN) return;
    float xv = x[n];
    const float* Y = g_Y + (size_t)n * 48;
    float h[16];
#pragma unroll
    for (int f = 0; f < 16; f++) h[f] = 0.f;
#pragma unroll
    for (int k = 0; k < 3; k++) {
        float y[16];
#pragma unroll
        for (int q = 0; q < 16; q++) y[q] = Y[k * 16 + q];
#pragma unroll
        for (int p = 0; p < 16; p++) {
            float o = xv * srw[k * 16 + p] + sb[k * 16 + p];
#pragma unroll
            for (int q = 0; q < 16; q++) o += y[q] * sW[k * 256 + q * 16 + p];
            h[p] += fmaxf(o, 0.f);
        }
    }
#pragma unroll
    for (int f = 0; f < 16; f++) {
        float a = h[f] * (1.f / 3.f) * sscale[f] + sshift[f];
        h[f] = fmaxf(a, 0.f);
    }
    float z[3], r2[3];
#pragma unroll
    for (int k = 0; k < 3; k++) {
        float za = 0.f, ra = 0.f;
#pragma unroll
        for (int f = 0; f < 16; f++) {
            za += h[f] * siw2[k * 16 + f];
            ra += h[f] * srw2[k * 16 + f];
        }
        z[k] = za;
        r2[k] = ra + sb2[k];
    }
    *(float4*)(g_Z2a + (size_t)n * 4)   = make_float4(z[0], z[1], z[2], 0.f);
    *(float4*)(g_root2 + (size_t)n * 4) = make_float4(r2[0], r2[1], r2[2], 0.f);
}

// ---------------- conv2 gather + fused node update -------------------------
// STEP 0: Z2b = L Z2a + root2
// STEP 1: Z2a = w * (L Z2b) + root2
// STEP 2: Z2b = w * (L Z2a) + root2
// STEP 3: out = sigmoid(mean(w * (L Z2b) + root2))
// Ping/pong resolved IN DEVICE CODE — device globals must never be passed
// as kernel arguments from host (host shadow address + HMM paging!).
template <int STEP>
__global__ void __launch_bounds__(256) k_gath4(const float* __restrict__ w2,
                                               float* __restrict__ out) {
    const float* src = (STEP == 0 || STEP == 2) ? g_Z2a : g_Z2b;
    float* dst = (STEP == 1) ? g_Z2a : g_Z2b;
    int wid = (blockIdx.x * blockDim.x + threadIdx.x) >> 5;
    int lane = threadIdx.x & 31;
    if (wid >= NN) return;
    int beg = g_off[wid], end = g_off[wid + 1];
    float ax = 0.f, ay = 0.f, az = 0.f;
    for (int p = beg + lane; p < end; p += 32) {
        int2 ent = __ldg(&g_csr[p]);
        float w = __int_as_float(ent.y);
        float4 v = *(const float4*)(src + (size_t)ent.x * 4);
        ax += w * v.x; ay += w * v.y; az += w * v.z;
    }
#pragma unroll
    for (int o = 16; o; o >>= 1) {
        ax += __shfl_xor_sync(0xffffffffu, ax, o);
        ay += __shfl_xor_sync(0xffffffffu, ay, o);
        az += __shfl_xor_sync(0xffffffffu, az, o);
    }
    if (lane) return;
    float4 r = *(const float4*)(g_root2 + (size_t)wid * 4);
    if (STEP >= 1) {
        ax *= __ldg(w2 + 0); ay *= __ldg(w2 + 1); az *= __ldg(w2 + 2);
    }
    ax += r.x; ay += r.y; az += r.z;
    if (STEP == 3) {
        float s = (ax + ay + az) * (1.f / 3.f);
        out[wid] = 1.f / (1.f + expf(-s));
    } else {
        *(float4*)(dst + (size_t)wid * 4) = make_float4(ax, ay, az, 0.f);
    }
}

// ---------------- launch ---------------------------------------------------
extern "C" void kernel_launch(void* const* d_in, const int* in_sizes, int n_in,
                              void* d_out, int out_size) {
    const float* x     = (const float*)d_in[0];
    const int*   ei    = (const int*)d_in[1];
    const float* ew    = (const float*)d_in[2];
    const float* c1_iw = (const float*)d_in[3];
    const float* c1_w  = (const float*)d_in[4];
    const float* c1_rw = (const float*)d_in[5];
    const float* c1_b  = (const float*)d_in[6];
    const float* bn_g  = (const float*)d_in[7];
    const float* bn_b  = (const float*)d_in[8];
    const float* bn_m  = (const float*)d_in[9];
    const float* bn_v  = (const float*)d_in[10];
    const float* c2_iw = (const float*)d_in[11];
    const float* c2_w  = (const float*)d_in[12];
    const float* c2_rw = (const float*)d_in[13];
    const float* c2_b  = (const float*)d_in[14];
    float* out = (float*)d_out;

    const int* row = ei;
    const int* col = ei + EE;

    const int GN = (NN + 255) / 256;
    const int GE = (EE + 255) / 256;
    const int NB1 = (NN + 1023) / 1024;        // 98
    const int GW = (NN * 32 + 255) / 256;      // warp-per-node grids
    const int G48 = (NN + 31) / 32;            // 3125 blocks of 384

    // CSR build (by col), gcn_norm fused into scatter
    k_zero<<<GN, 256>>>();
    k_hist<<<GE, 256>>>(col, ew);
    k_dis<<<GN, 256>>>();
    k_scan1<<<NB1, 1024>>>();
    k_scan2<<<1, 32>>>(NB1);
    k_scan3<<<GN, 256>>>();
    k_scatter<<<GE, 256>>>(row, col, ew);

    // conv1: rank-1 first iteration, then 3 gather+node iterations
    k_Lx<<<GW, 256>>>(x);
    k_post0<<<GN, 256>>>(x, c1_iw, c1_rw, c1_b);
    for (int t = 0; t < 3; t++) {
        k_gath48<<<G48, 384>>>();
        if (t < 2)
            k_node_mid<<<GN, 256>>>(x, c1_w, c1_rw, c1_b);
        else
            k_node_last<<<GN, 256>>>(x, c1_w, c1_rw, c1_b, bn_g, bn_b, bn_m, bn_v,
                                     c2_iw, c2_rw, c2_b);
    }

    // conv2: 4 gather iterations, node updates fused into epilogue
    k_gath4<0><<<GW, 256>>>(c2_w, out);
    k_gath4<1><<<GW, 256>>>(c2_w, out);
    k_gath4<2><<<GW, 256>>>(c2_w, out);
    k_gath4<3><<<GW, 256>>>(c2_w, out);

    (void)in_sizes; (void)n_in; (void)out_size;
}